// round 13
// baseline (speedup 1.0000x reference)
#include <cuda_runtime.h>
#include <cstdint>

#define MM   6
#define BB   128
#define TT   32
#define DINN 64
#define HHH  512
#define EEE  512
#define NEMB 32

#define MAXC       80
#define ROWS       64     // token rows per block: 2 batches x 32
#define XS_STRIDE  68     // words; mod 32 = 4 -> conflict-free A-fragment LDS (tf32 GEMM1)
#define HS2_STRIDE 260    // fp16x2 words per row; mod 32 = 4 -> conflict-free A-frag LDS

// per-warp weight ring
#define WROW_B   160
#define WSTG1_B  (8 * WROW_B)       // 1280: GEMM1 tf32 k8 stage
#define WSTG2_B  (16 * WROW_B)      // 2560: GEMM2 fp16 k16 stage (f32 weights)
#define WRING_B  5120               // max(3*WSTG1_B, 2*WSTG2_B)
#define XS_BYTES (ROWS * XS_STRIDE * 4)     // 17408
#define HS_BYTES (ROWS * HS2_STRIDE * 4)    // 66560
#define WR_OFF_B (XS_BYTES + HS_BYTES)      // 83968
#define SMEM_BYTES (WR_OFF_B + 16 * WRING_B)  // 165888

__device__ int g_chunk_b0[MAXC];
__device__ int g_chunk_b1[MAXC];
__device__ int g_chunk_e [MAXC];
__device__ int g_nchunks;

__global__ void pmst_prepass(const int* __restrict__ emb_ids) {
    __shared__ int se[BB];
    for (int i = threadIdx.x; i < BB; i += 32) se[i] = emb_ids[i];
    __syncwarp();
    const int e = threadIdx.x;             // 0..31
    int cnt = 0;
    for (int b = 0; b < BB; b++) cnt += (se[b] == e);
    int pairs = (cnt + 1) >> 1;
    int off = pairs;
    #pragma unroll
    for (int d = 1; d < 32; d <<= 1) {
        int v = __shfl_up_sync(0xFFFFFFFFu, off, d);
        if (e >= d) off += v;
    }
    if (e == 31) g_nchunks = off;
    int idx = off - pairs;
    int prev = -1;
    for (int b = 0; b < BB; b++) {
        if (se[b] == e) {
            if (prev < 0) prev = b;
            else { g_chunk_b0[idx] = prev; g_chunk_b1[idx] = b; g_chunk_e[idx] = e; idx++; prev = -1; }
        }
    }
    if (prev >= 0) { g_chunk_b0[idx] = prev; g_chunk_b1[idx] = prev; g_chunk_e[idx] = e; }
}

__device__ __forceinline__ uint32_t f2tf(float f) {
    uint32_t r; asm("cvt.rna.tf32.f32 %0, %1;" : "=r"(r) : "f"(f)); return r;
}
// pack two f32 -> fp16x2: lo = cvt(blo), hi = cvt(ahi)
__device__ __forceinline__ uint32_t packf16(float ahi, float blo) {
    uint32_t r; asm("cvt.rn.f16x2.f32 %0, %1, %2;" : "=r"(r) : "f"(ahi), "f"(blo)); return r;
}

__device__ __forceinline__ void mma8(float* d, const uint32_t* a, uint32_t b0, uint32_t b1) {
    asm volatile(
        "mma.sync.aligned.m16n8k8.row.col.f32.tf32.tf32.f32 "
        "{%0,%1,%2,%3}, {%4,%5,%6,%7}, {%8,%9}, {%0,%1,%2,%3};"
        : "+f"(d[0]), "+f"(d[1]), "+f"(d[2]), "+f"(d[3])
        : "r"(a[0]), "r"(a[1]), "r"(a[2]), "r"(a[3]), "r"(b0), "r"(b1));
}
__device__ __forceinline__ void mma16(float* d, const uint32_t* a, uint32_t b0, uint32_t b1) {
    asm volatile(
        "mma.sync.aligned.m16n8k16.row.col.f32.f16.f16.f32 "
        "{%0,%1,%2,%3}, {%4,%5,%6,%7}, {%8,%9}, {%0,%1,%2,%3};"
        : "+f"(d[0]), "+f"(d[1]), "+f"(d[2]), "+f"(d[3])
        : "r"(a[0]), "r"(a[1]), "r"(a[2]), "r"(a[3]), "r"(b0), "r"(b1));
}

#define CP_COMMIT() asm volatile("cp.async.commit_group;" ::: "memory")
#define CP_WAIT1()  asm volatile("cp.async.wait_group 1;" ::: "memory")
#define CP_WAIT0()  asm volatile("cp.async.wait_group 0;" ::: "memory")

// GEMM1 (k8): lane (g,tg) copies rows (tg, tg+4), cols 4g..4g+3 (2x16B)
__device__ __forceinline__ void issue_wslab8(uint32_t stage, const float* __restrict__ wrow,
                                             int g, int tg) {
    const float* sA = wrow + (long)tg * 512 + 4 * g;
    const float* sB = sA + 4 * 512;
    const uint32_t dA = stage + (uint32_t)(tg * WROW_B + g * 16);
    const uint32_t dB = dA + 4 * WROW_B;
    asm volatile("cp.async.cg.shared.global [%0], [%1], 16;" :: "r"(dA), "l"(sA) : "memory");
    asm volatile("cp.async.cg.shared.global [%0], [%1], 16;" :: "r"(dB), "l"(sB) : "memory");
}
// GEMM2 (k16): lane (g,tg) copies rows (2tg, 2tg+1, 2tg+8, 2tg+9), cols 4g..4g+3 (4x16B)
__device__ __forceinline__ void issue_wslab16(uint32_t stage, const float* __restrict__ wrow,
                                              int g, int tg) {
    const float* s0 = wrow + (long)(2 * tg) * 512 + 4 * g;
    const float* s1 = s0 + 512;
    const float* s2 = s0 + 8 * 512;
    const float* s3 = s2 + 512;
    const uint32_t d0 = stage + (uint32_t)(2 * tg * WROW_B + g * 16);
    asm volatile("cp.async.cg.shared.global [%0], [%1], 16;" :: "r"(d0),               "l"(s0) : "memory");
    asm volatile("cp.async.cg.shared.global [%0], [%1], 16;" :: "r"(d0 + WROW_B),      "l"(s1) : "memory");
    asm volatile("cp.async.cg.shared.global [%0], [%1], 16;" :: "r"(d0 + 8 * WROW_B),  "l"(s2) : "memory");
    asm volatile("cp.async.cg.shared.global [%0], [%1], 16;" :: "r"(d0 + 9 * WROW_B),  "l"(s3) : "memory");
}

__device__ __forceinline__ void lds128(float4& v, uint32_t addr) {
    asm volatile("ld.shared.v4.f32 {%0,%1,%2,%3}, [%4];"
                 : "=f"(v.x), "=f"(v.y), "=f"(v.z), "=f"(v.w) : "r"(addr));
}

// grid = (MAXC, MM); block = 512 threads (16 warps). Warp tile: 64 rows x 32 cols.
// Column perm: logical mma col (8nt + j) == physical col (ncol0 + 4j + nt).
// GEMM1: tf32 k8 (as R9). GEMM2: fp16 k16, H stored fp16x2 (k-pairs packed).
__global__ __launch_bounds__(512, 1) void pmst_mma_kernel(
    const float* __restrict__ state,   // [B, T, M*DIN]
    const float* __restrict__ W1,      // [M, NEMB, DIN, H]
    const float* __restrict__ b1,      // [M, NEMB, H]
    const float* __restrict__ W2,      // [M, NEMB, H, E]
    const float* __restrict__ b2,      // [M, NEMB, E]
    const float* __restrict__ te,      // [M, E]
    float* __restrict__ out)           // [B, M*T, E]
{
    const int c = blockIdx.x;
    if (c >= g_nchunks) return;
    const int m   = blockIdx.y;
    const int e   = g_chunk_e[c];
    const int b0  = g_chunk_b0[c];
    const int b1v = g_chunk_b1[c];

    extern __shared__ uint32_t smu[];
    uint32_t* Xs  = smu;                         // [ROWS][XS_STRIDE]  tf32 bits
    uint32_t* Hs2 = smu + ROWS * XS_STRIDE;      // [ROWS][HS2_STRIDE] fp16x2 k-pairs
    uint32_t smem_base;
    asm("{ .reg .u64 t; cvta.to.shared.u64 t, %1; cvt.u32.u64 %0, t; }"
        : "=r"(smem_base) : "l"((const void*)smu));

    const int tid  = threadIdx.x;
    const int wid  = tid >> 5;
    const int lane = tid & 31;
    const int g    = lane >> 2;    // 0..7
    const int tg   = lane & 3;     // 0..3

    const uint32_t wring = smem_base + WR_OFF_B + wid * WRING_B;

    const long me = (long)m * NEMB + e;
    const float* W1p = W1 + me * (DINN * HHH);
    const float* W2p = W2 + me * ((long)HHH * EEE);
    const float* b1p = b1 + me * HHH;
    const float* b2p = b2 + me * EEE;
    const float* tep = te + (long)m * EEE;

    const int ncol0 = wid * 32;
    const float* w1base = W1p + ncol0;
    const float* w2base = W2p + ncol0;
    float acc[4][4][4];   // [m-tile][n-tile][frag]

    // ---- GEMM1 prologue: stages 0,1 in flight ----
    issue_wslab8(wring + 0 * WSTG1_B, w1base,           g, tg); CP_COMMIT();
    issue_wslab8(wring + 1 * WSTG1_B, w1base + 8 * HHH, g, tg); CP_COMMIT();

    // ---- Stage X (tf32) ----
    #pragma unroll
    for (int i = tid; i < ROWS * DINN; i += 512) {
        const int tr = i >> 6, k = i & 63;
        const int bb = (tr < TT) ? b0 : b1v;
        const int t  = tr & (TT - 1);
        Xs[tr * XS_STRIDE + k] =
            f2tf(__ldg(state + ((long)bb * TT + t) * (MM * DINN) + m * DINN + k));
    }
    __syncthreads();

    // ================= GEMM1 (tf32): H = relu(X @ W1 + b1) =================
    #pragma unroll
    for (int mt = 0; mt < 4; mt++)
        #pragma unroll
        for (int nt = 0; nt < 4; nt++)
            #pragma unroll
            for (int i = 0; i < 4; i++) acc[mt][nt][i] = 0.f;
    {
        int stg = 0;
        #pragma unroll
        for (int kc = 0; kc < 8; kc++) {
            CP_WAIT1();
            if (kc + 2 < 8) issue_wslab8(wring + ((stg + 2) % 3) * WSTG1_B,
                                         w1base + (long)(kc + 2) * 8 * HHH, g, tg);
            CP_COMMIT();

            uint32_t a[4][4];
            {
                const uint32_t* xb = Xs + g * XS_STRIDE + tg + kc * 8;
                #pragma unroll
                for (int mt = 0; mt < 4; mt++) {
                    const uint32_t* xp = xb + mt * 16 * XS_STRIDE;
                    a[mt][0] = xp[0];
                    a[mt][1] = xp[8 * XS_STRIDE];
                    a[mt][2] = xp[4];
                    a[mt][3] = xp[8 * XS_STRIDE + 4];
                }
            }
            float4 v0, v1;
            const uint32_t baseA = wring + stg * WSTG1_B + (uint32_t)(tg * WROW_B + g * 16);
            lds128(v0, baseA);
            lds128(v1, baseA + 4 * WROW_B);
            const uint32_t w0[4]  = { f2tf(v0.x), f2tf(v0.y), f2tf(v0.z), f2tf(v0.w) };
            const uint32_t w1f[4] = { f2tf(v1.x), f2tf(v1.y), f2tf(v1.z), f2tf(v1.w) };
            #pragma unroll
            for (int nt = 0; nt < 4; nt++)
                #pragma unroll
                for (int mt = 0; mt < 4; mt++) mma8(acc[mt][nt], a[mt], w0[nt], w1f[nt]);
            if (++stg == 3) stg = 0;
        }
    }

    // ---- GEMM2 prologue (k16 slabs 0,1; overlaps epilogue1 + barrier) ----
    CP_WAIT0();
    issue_wslab16(wring + 0 * WSTG2_B, w2base,            g, tg); CP_COMMIT();
    issue_wslab16(wring + 1 * WSTG2_B, w2base + 16 * EEE, g, tg); CP_COMMIT();

    // ---- epilogue1: relu + bias -> Hs2 (fp16x2, k-pairs along physical cols) ----
    {
        const int pc = ncol0 + 8 * tg;        // multiple of 8 -> word base pc/2
        const float4 bL = __ldg((const float4*)(b1p + pc));
        const float4 bH = __ldg((const float4*)(b1p + pc + 4));
        #pragma unroll
        for (int mt = 0; mt < 4; mt++) {
            const int r0 = mt * 16 + g;
            const int r1 = r0 + 8;
            // cols pc+0..3 = acc[nt][f] + bL[nt]; pc+4..7 = acc[nt][f+1] + bH[nt]
            uint4 wv;
            wv.x = packf16(fmaxf(acc[mt][1][0] + bL.y, 0.f), fmaxf(acc[mt][0][0] + bL.x, 0.f));
            wv.y = packf16(fmaxf(acc[mt][3][0] + bL.w, 0.f), fmaxf(acc[mt][2][0] + bL.z, 0.f));
            wv.z = packf16(fmaxf(acc[mt][1][1] + bH.y, 0.f), fmaxf(acc[mt][0][1] + bH.x, 0.f));
            wv.w = packf16(fmaxf(acc[mt][3][1] + bH.w, 0.f), fmaxf(acc[mt][2][1] + bH.z, 0.f));
            *(uint4*)(Hs2 + r0 * HS2_STRIDE + pc / 2) = wv;
            wv.x = packf16(fmaxf(acc[mt][1][2] + bL.y, 0.f), fmaxf(acc[mt][0][2] + bL.x, 0.f));
            wv.y = packf16(fmaxf(acc[mt][3][2] + bL.w, 0.f), fmaxf(acc[mt][2][2] + bL.z, 0.f));
            wv.z = packf16(fmaxf(acc[mt][1][3] + bH.y, 0.f), fmaxf(acc[mt][0][3] + bH.x, 0.f));
            wv.w = packf16(fmaxf(acc[mt][3][3] + bH.w, 0.f), fmaxf(acc[mt][2][3] + bH.z, 0.f));
            *(uint4*)(Hs2 + r1 * HS2_STRIDE + pc / 2) = wv;
        }
    }
    __syncthreads();

    // ================= GEMM2 (fp16 k16): Z = H @ W2 + b2 + te =================
    #pragma unroll
    for (int mt = 0; mt < 4; mt++)
        #pragma unroll
        for (int nt = 0; nt < 4; nt++)
            #pragma unroll
            for (int i = 0; i < 4; i++) acc[mt][nt][i] = 0.f;
    {
        #pragma unroll 4
        for (int kc = 0; kc < 32; kc++) {     // k16 chunks
            CP_WAIT1();
            // A fragments: words kp = kc*8 + {tg, 4+tg}, rows g(+8) per m-tile
            uint32_t a[4][4];
            {
                const uint32_t* hb = Hs2 + g * HS2_STRIDE + kc * 8 + tg;
                #pragma unroll
                for (int mt = 0; mt < 4; mt++) {
                    const uint32_t* hp = hb + mt * 16 * HS2_STRIDE;
                    a[mt][0] = hp[0];
                    a[mt][1] = hp[8 * HS2_STRIDE];
                    a[mt][2] = hp[4];
                    a[mt][3] = hp[8 * HS2_STRIDE + 4];
                }
            }
            // weight rows 2tg, 2tg+1, 2tg+8, 2tg+9 (f32), cols 4g..4g+3
            float4 v0, v1, v2, v3;
            const uint32_t baseA = wring + (kc & 1) * WSTG2_B + (uint32_t)(2 * tg * WROW_B + g * 16);
            lds128(v0, baseA);
            lds128(v1, baseA + WROW_B);
            lds128(v2, baseA + 8 * WROW_B);
            lds128(v3, baseA + 9 * WROW_B);
            if (kc + 2 < 32) issue_wslab16(wring + (kc & 1) * WSTG2_B,
                                           w2base + (long)(kc + 2) * 16 * EEE, g, tg);
            CP_COMMIT();

            const uint32_t bf0[4] = { packf16(v1.x, v0.x), packf16(v1.y, v0.y),
                                      packf16(v1.z, v0.z), packf16(v1.w, v0.w) };
            const uint32_t bf1[4] = { packf16(v3.x, v2.x), packf16(v3.y, v2.y),
                                      packf16(v3.z, v2.z), packf16(v3.w, v2.w) };
            #pragma unroll
            for (int nt = 0; nt < 4; nt++)
                #pragma unroll
                for (int mt = 0; mt < 4; mt++)
                    mma16(acc[mt][nt], a[mt], bf0[nt], bf1[nt]);
        }
    }

    // ---- epilogue2: out[b, m*T + t, physical col] ----
    {
        const int pc = ncol0 + 8 * tg;
        const float4 bL = __ldg((const float4*)(b2p + pc));
        const float4 bH = __ldg((const float4*)(b2p + pc + 4));
        const float4 tL = __ldg((const float4*)(tep + pc));
        const float4 tH = __ldg((const float4*)(tep + pc + 4));
        const float4 aL = make_float4(bL.x + tL.x, bL.y + tL.y, bL.z + tL.z, bL.w + tL.w);
        const float4 aH = make_float4(bH.x + tH.x, bH.y + tH.y, bH.z + tH.z, bH.w + tH.w);
        float* op0 = out + ((long)b0  * MM + m) * TT * EEE;
        float* op1 = out + ((long)b1v * MM + m) * TT * EEE;
        #pragma unroll
        for (int mt = 0; mt < 4; mt++) {
            const int r0 = mt * 16 + g;
            const int r1 = r0 + 8;
            float* p0 = ((r0 < TT) ? op0 : op1) + (long)(r0 & (TT - 1)) * EEE + pc;
            float* p1 = ((r1 < TT) ? op0 : op1) + (long)(r1 & (TT - 1)) * EEE + pc;
            *(float4*)p0 = make_float4(acc[mt][0][0] + aL.x, acc[mt][1][0] + aL.y,
                                       acc[mt][2][0] + aL.z, acc[mt][3][0] + aL.w);
            *(float4*)(p0 + 4) = make_float4(acc[mt][0][1] + aH.x, acc[mt][1][1] + aH.y,
                                             acc[mt][2][1] + aH.z, acc[mt][3][1] + aH.w);
            *(float4*)p1 = make_float4(acc[mt][0][2] + aL.x, acc[mt][1][2] + aL.y,
                                       acc[mt][2][2] + aL.z, acc[mt][3][2] + aL.w);
            *(float4*)(p1 + 4) = make_float4(acc[mt][0][3] + aH.x, acc[mt][1][3] + aH.y,
                                             acc[mt][2][3] + aH.z, acc[mt][3][3] + aH.w);
        }
    }
}

extern "C" void kernel_launch(void* const* d_in, const int* in_sizes, int n_in,
                              void* d_out, int out_size)
{
    const float* state   = (const float*)d_in[0];
    const int*   emb_ids = (const int*)  d_in[1];
    const float* W1      = (const float*)d_in[2];
    const float* b1      = (const float*)d_in[3];
    const float* W2      = (const float*)d_in[4];
    const float* b2      = (const float*)d_in[5];
    const float* te      = (const float*)d_in[6];
    float*       out     = (float*)d_out;

    pmst_prepass<<<1, 32>>>(emb_ids);

    cudaFuncSetAttribute(pmst_mma_kernel,
                         cudaFuncAttributeMaxDynamicSharedMemorySize, SMEM_BYTES);

    dim3 grid(MAXC, MM);
    pmst_mma_kernel<<<grid, 512, SMEM_BYTES>>>(state, emb_ids ? W1 : W1, b1, W2, b2, te, out);
}

// round 14
// speedup vs baseline: 1.4951x; 1.4951x over previous
#include <cuda_runtime.h>
#include <cstdint>

#define MM   6
#define BB   128
#define TT   32
#define DINN 64
#define HHH  512
#define EEE  512
#define NEMB 32

#define MAXC       80
#define ROWS       64     // token rows per block: 2 batches x 32
#define XS_STRIDE  68     // words; mod 32 = 4 -> conflict-free A-fragment LDS (tf32 GEMM1)
#define HS2_STRIDE 260    // fp16x2 words per row; mod 32 = 4 -> conflict-free A-frag LDS

// per-warp weight ring (shared region for both GEMMs)
#define WROW1_B  160                 // GEMM1 k8 stage row stride
#define WSTG1_B  (8 * WROW1_B)       // 1280
#define WROW2_B  176                 // GEMM2 k16 stage row stride (conflict-free LDS.128)
#define WSTG2_B  (16 * WROW2_B)      // 2816
#define WRING_B  (3 * WSTG2_B)       // 8448 (also covers 3*WSTG1_B)
#define XS_BYTES (ROWS * XS_STRIDE * 4)     // 17408
#define HS_BYTES (ROWS * HS2_STRIDE * 4)    // 66560
#define WR_OFF_B (XS_BYTES + HS_BYTES)      // 83968
#define SMEM_BYTES (WR_OFF_B + 16 * WRING_B)  // 219136

__device__ int g_chunk_b0[MAXC];
__device__ int g_chunk_b1[MAXC];
__device__ int g_chunk_e [MAXC];
__device__ int g_nchunks;

__global__ void pmst_prepass(const int* __restrict__ emb_ids) {
    __shared__ int se[BB];
    for (int i = threadIdx.x; i < BB; i += 32) se[i] = emb_ids[i];
    __syncwarp();
    const int e = threadIdx.x;             // 0..31
    int cnt = 0;
    for (int b = 0; b < BB; b++) cnt += (se[b] == e);
    int pairs = (cnt + 1) >> 1;
    int off = pairs;
    #pragma unroll
    for (int d = 1; d < 32; d <<= 1) {
        int v = __shfl_up_sync(0xFFFFFFFFu, off, d);
        if (e >= d) off += v;
    }
    if (e == 31) g_nchunks = off;
    int idx = off - pairs;
    int prev = -1;
    for (int b = 0; b < BB; b++) {
        if (se[b] == e) {
            if (prev < 0) prev = b;
            else { g_chunk_b0[idx] = prev; g_chunk_b1[idx] = b; g_chunk_e[idx] = e; idx++; prev = -1; }
        }
    }
    if (prev >= 0) { g_chunk_b0[idx] = prev; g_chunk_b1[idx] = prev; g_chunk_e[idx] = e; }
}

__device__ __forceinline__ uint32_t f2tf(float f) {
    uint32_t r; asm("cvt.rna.tf32.f32 %0, %1;" : "=r"(r) : "f"(f)); return r;
}
// pack two f32 -> fp16x2: lo = cvt(blo), hi = cvt(ahi)
__device__ __forceinline__ uint32_t packf16(float ahi, float blo) {
    uint32_t r; asm("cvt.rn.f16x2.f32 %0, %1, %2;" : "=r"(r) : "f"(ahi), "f"(blo)); return r;
}

__device__ __forceinline__ void mma8(float* d, const uint32_t* a, uint32_t b0, uint32_t b1) {
    asm volatile(
        "mma.sync.aligned.m16n8k8.row.col.f32.tf32.tf32.f32 "
        "{%0,%1,%2,%3}, {%4,%5,%6,%7}, {%8,%9}, {%0,%1,%2,%3};"
        : "+f"(d[0]), "+f"(d[1]), "+f"(d[2]), "+f"(d[3])
        : "r"(a[0]), "r"(a[1]), "r"(a[2]), "r"(a[3]), "r"(b0), "r"(b1));
}
__device__ __forceinline__ void mma16(float* d, const uint32_t* a, uint32_t b0, uint32_t b1) {
    asm volatile(
        "mma.sync.aligned.m16n8k16.row.col.f32.f16.f16.f32 "
        "{%0,%1,%2,%3}, {%4,%5,%6,%7}, {%8,%9}, {%0,%1,%2,%3};"
        : "+f"(d[0]), "+f"(d[1]), "+f"(d[2]), "+f"(d[3])
        : "r"(a[0]), "r"(a[1]), "r"(a[2]), "r"(a[3]), "r"(b0), "r"(b1));
}

#define CP_COMMIT() asm volatile("cp.async.commit_group;" ::: "memory")
#define CP_WAIT1()  asm volatile("cp.async.wait_group 1;" ::: "memory")
#define CP_WAIT0()  asm volatile("cp.async.wait_group 0;" ::: "memory")

// GEMM1 (k8): lane (g,tg) copies rows (tg, tg+4), cols 4g..4g+3 (2x16B)
__device__ __forceinline__ void issue_wslab8(uint32_t stage, const float* __restrict__ wrow,
                                             int g, int tg) {
    const float* sA = wrow + (long)tg * 512 + 4 * g;
    const float* sB = sA + 4 * 512;
    const uint32_t dA = stage + (uint32_t)(tg * WROW1_B + g * 16);
    const uint32_t dB = dA + 4 * WROW1_B;
    asm volatile("cp.async.cg.shared.global [%0], [%1], 16;" :: "r"(dA), "l"(sA) : "memory");
    asm volatile("cp.async.cg.shared.global [%0], [%1], 16;" :: "r"(dB), "l"(sB) : "memory");
}
// GEMM2 (k16): lane (g,tg) copies rows (2tg, 2tg+1, 2tg+8, 2tg+9), cols 4g..4g+3 (4x16B)
__device__ __forceinline__ void issue_wslab16(uint32_t stage, const float* __restrict__ wrow,
                                              int g, int tg) {
    const float* s0 = wrow + (long)(2 * tg) * 512 + 4 * g;
    const float* s1 = s0 + 512;
    const float* s2 = s0 + 8 * 512;
    const float* s3 = s2 + 512;
    const uint32_t d0 = stage + (uint32_t)(2 * tg * WROW2_B + g * 16);
    asm volatile("cp.async.cg.shared.global [%0], [%1], 16;" :: "r"(d0),               "l"(s0) : "memory");
    asm volatile("cp.async.cg.shared.global [%0], [%1], 16;" :: "r"(d0 + WROW2_B),     "l"(s1) : "memory");
    asm volatile("cp.async.cg.shared.global [%0], [%1], 16;" :: "r"(d0 + 8 * WROW2_B), "l"(s2) : "memory");
    asm volatile("cp.async.cg.shared.global [%0], [%1], 16;" :: "r"(d0 + 9 * WROW2_B), "l"(s3) : "memory");
}

__device__ __forceinline__ void lds128(float4& v, uint32_t addr) {
    asm volatile("ld.shared.v4.f32 {%0,%1,%2,%3}, [%4];"
                 : "=f"(v.x), "=f"(v.y), "=f"(v.z), "=f"(v.w) : "r"(addr));
}

// grid = (MAXC, MM); block = 512 threads (16 warps). Warp tile: 64 rows x 32 cols.
// Column perm: logical mma col (8nt + j) == physical col (ncol0 + 4j + nt).
// GEMM1: tf32 k8 (R9 structure). GEMM2: fp16 k16, H stored fp16x2, R9 pipeline discipline.
__global__ __launch_bounds__(512, 1) void pmst_mma_kernel(
    const float* __restrict__ state,   // [B, T, M*DIN]
    const float* __restrict__ W1,      // [M, NEMB, DIN, H]
    const float* __restrict__ b1,      // [M, NEMB, H]
    const float* __restrict__ W2,      // [M, NEMB, H, E]
    const float* __restrict__ b2,      // [M, NEMB, E]
    const float* __restrict__ te,      // [M, E]
    float* __restrict__ out)           // [B, M*T, E]
{
    const int c = blockIdx.x;
    if (c >= g_nchunks) return;
    const int m   = blockIdx.y;
    const int e   = g_chunk_e[c];
    const int b0  = g_chunk_b0[c];
    const int b1v = g_chunk_b1[c];

    extern __shared__ uint32_t smu[];
    uint32_t* Xs  = smu;                         // [ROWS][XS_STRIDE]  tf32 bits
    uint32_t* Hs2 = smu + ROWS * XS_STRIDE;      // [ROWS][HS2_STRIDE] fp16x2 k-pairs
    uint32_t smem_base;
    asm("{ .reg .u64 t; cvta.to.shared.u64 t, %1; cvt.u32.u64 %0, t; }"
        : "=r"(smem_base) : "l"((const void*)smu));

    const int tid  = threadIdx.x;
    const int wid  = tid >> 5;
    const int lane = tid & 31;
    const int g    = lane >> 2;    // 0..7
    const int tg   = lane & 3;     // 0..3

    const uint32_t wring = smem_base + WR_OFF_B + wid * WRING_B;

    const long me = (long)m * NEMB + e;
    const float* W1p = W1 + me * (DINN * HHH);
    const float* W2p = W2 + me * ((long)HHH * EEE);
    const float* b1p = b1 + me * HHH;
    const float* b2p = b2 + me * EEE;
    const float* tep = te + (long)m * EEE;

    const int ncol0 = wid * 32;
    const float* w1base = W1p + ncol0;
    const float* w2base = W2p + ncol0;
    float acc[4][4][4];   // [m-tile][n-tile][frag]

    // ---- GEMM1 prologue: stages 0,1 in flight ----
    issue_wslab8(wring + 0 * WSTG1_B, w1base,           g, tg); CP_COMMIT();
    issue_wslab8(wring + 1 * WSTG1_B, w1base + 8 * HHH, g, tg); CP_COMMIT();

    // ---- Stage X (tf32) ----
    #pragma unroll
    for (int i = tid; i < ROWS * DINN; i += 512) {
        const int tr = i >> 6, k = i & 63;
        const int bb = (tr < TT) ? b0 : b1v;
        const int t  = tr & (TT - 1);
        Xs[tr * XS_STRIDE + k] =
            f2tf(__ldg(state + ((long)bb * TT + t) * (MM * DINN) + m * DINN + k));
    }
    __syncthreads();

    // ================= GEMM1 (tf32): H = relu(X @ W1 + b1) =================
    #pragma unroll
    for (int mt = 0; mt < 4; mt++)
        #pragma unroll
        for (int nt = 0; nt < 4; nt++)
            #pragma unroll
            for (int i = 0; i < 4; i++) acc[mt][nt][i] = 0.f;
    {
        int stg = 0;
        #pragma unroll
        for (int kc = 0; kc < 8; kc++) {
            CP_WAIT1();
            if (kc + 2 < 8) issue_wslab8(wring + ((stg + 2) % 3) * WSTG1_B,
                                         w1base + (long)(kc + 2) * 8 * HHH, g, tg);
            CP_COMMIT();

            uint32_t a[4][4];
            {
                const uint32_t* xb = Xs + g * XS_STRIDE + tg + kc * 8;
                #pragma unroll
                for (int mt = 0; mt < 4; mt++) {
                    const uint32_t* xp = xb + mt * 16 * XS_STRIDE;
                    a[mt][0] = xp[0];
                    a[mt][1] = xp[8 * XS_STRIDE];
                    a[mt][2] = xp[4];
                    a[mt][3] = xp[8 * XS_STRIDE + 4];
                }
            }
            float4 v0, v1;
            const uint32_t baseA = wring + stg * WSTG1_B + (uint32_t)(tg * WROW1_B + g * 16);
            lds128(v0, baseA);
            lds128(v1, baseA + 4 * WROW1_B);
            const uint32_t w0[4]  = { f2tf(v0.x), f2tf(v0.y), f2tf(v0.z), f2tf(v0.w) };
            const uint32_t w1f[4] = { f2tf(v1.x), f2tf(v1.y), f2tf(v1.z), f2tf(v1.w) };
            #pragma unroll
            for (int nt = 0; nt < 4; nt++)
                #pragma unroll
                for (int mt = 0; mt < 4; mt++) mma8(acc[mt][nt], a[mt], w0[nt], w1f[nt]);
            if (++stg == 3) stg = 0;
        }
    }

    // ---- GEMM2 prologue (k16 slabs 0,1; overlaps epilogue1 + barrier) ----
    CP_WAIT0();
    issue_wslab16(wring + 0 * WSTG2_B, w2base,            g, tg); CP_COMMIT();
    issue_wslab16(wring + 1 * WSTG2_B, w2base + 16 * EEE, g, tg); CP_COMMIT();

    // ---- epilogue1: relu + bias -> Hs2 (fp16x2, k-pairs along physical cols) ----
    {
        const int pc = ncol0 + 8 * tg;        // multiple of 8 -> word base pc/2
        const float4 bL = __ldg((const float4*)(b1p + pc));
        const float4 bH = __ldg((const float4*)(b1p + pc + 4));
        #pragma unroll
        for (int mt = 0; mt < 4; mt++) {
            const int r0 = mt * 16 + g;
            const int r1 = r0 + 8;
            uint4 wv;
            wv.x = packf16(fmaxf(acc[mt][1][0] + bL.y, 0.f), fmaxf(acc[mt][0][0] + bL.x, 0.f));
            wv.y = packf16(fmaxf(acc[mt][3][0] + bL.w, 0.f), fmaxf(acc[mt][2][0] + bL.z, 0.f));
            wv.z = packf16(fmaxf(acc[mt][1][1] + bH.y, 0.f), fmaxf(acc[mt][0][1] + bH.x, 0.f));
            wv.w = packf16(fmaxf(acc[mt][3][1] + bH.w, 0.f), fmaxf(acc[mt][2][1] + bH.z, 0.f));
            *(uint4*)(Hs2 + r0 * HS2_STRIDE + pc / 2) = wv;
            wv.x = packf16(fmaxf(acc[mt][1][2] + bL.y, 0.f), fmaxf(acc[mt][0][2] + bL.x, 0.f));
            wv.y = packf16(fmaxf(acc[mt][3][2] + bL.w, 0.f), fmaxf(acc[mt][2][2] + bL.z, 0.f));
            wv.z = packf16(fmaxf(acc[mt][1][3] + bH.y, 0.f), fmaxf(acc[mt][0][3] + bH.x, 0.f));
            wv.w = packf16(fmaxf(acc[mt][3][3] + bH.w, 0.f), fmaxf(acc[mt][2][3] + bH.z, 0.f));
            *(uint4*)(Hs2 + r1 * HS2_STRIDE + pc / 2) = wv;
        }
    }
    __syncthreads();

    // ================= GEMM2 (fp16 k16): Z = H @ W2 + b2 + te =================
    #pragma unroll
    for (int mt = 0; mt < 4; mt++)
        #pragma unroll
        for (int nt = 0; nt < 4; nt++)
            #pragma unroll
            for (int i = 0; i < 4; i++) acc[mt][nt][i] = 0.f;
    {
        int stg = 0;
        #pragma unroll 4
        for (int kc = 0; kc < 32; kc++) {     // k16 chunks
            CP_WAIT1();
            // prefetch FIRST (R9 discipline), into the 3rd ring stage
            if (kc + 2 < 32) issue_wslab16(wring + ((stg + 2) % 3) * WSTG2_B,
                                           w2base + (long)(kc + 2) * 16 * EEE, g, tg);
            CP_COMMIT();

            // A fragments (fp16x2 words)
            uint32_t a[4][4];
            {
                const uint32_t* hb = Hs2 + g * HS2_STRIDE + kc * 8 + tg;
                #pragma unroll
                for (int mt = 0; mt < 4; mt++) {
                    const uint32_t* hp = hb + mt * 16 * HS2_STRIDE;
                    a[mt][0] = hp[0];
                    a[mt][1] = hp[8 * HS2_STRIDE];
                    a[mt][2] = hp[4];
                    a[mt][3] = hp[8 * HS2_STRIDE + 4];
                }
            }
            // weight rows 2tg, 2tg+1, 2tg+8, 2tg+9 (f32), cols 4g..4g+3 — conflict-free
            float4 v0, v1, v2, v3;
            const uint32_t baseA = wring + stg * WSTG2_B + (uint32_t)(2 * tg * WROW2_B + g * 16);
            lds128(v0, baseA);
            lds128(v1, baseA + WROW2_B);
            lds128(v2, baseA + 8 * WROW2_B);
            lds128(v3, baseA + 9 * WROW2_B);

            const uint32_t bf0[4] = { packf16(v1.x, v0.x), packf16(v1.y, v0.y),
                                      packf16(v1.z, v0.z), packf16(v1.w, v0.w) };
            const uint32_t bf1[4] = { packf16(v3.x, v2.x), packf16(v3.y, v2.y),
                                      packf16(v3.z, v2.z), packf16(v3.w, v2.w) };
            #pragma unroll
            for (int nt = 0; nt < 4; nt++)
                #pragma unroll
                for (int mt = 0; mt < 4; mt++)
                    mma16(acc[mt][nt], a[mt], bf0[nt], bf1[nt]);
            if (++stg == 3) stg = 0;
        }
    }

    // ---- epilogue2: out[b, m*T + t, physical col] ----
    {
        const int pc = ncol0 + 8 * tg;
        const float4 bL = __ldg((const float4*)(b2p + pc));
        const float4 bH = __ldg((const float4*)(b2p + pc + 4));
        const float4 tL = __ldg((const float4*)(tep + pc));
        const float4 tH = __ldg((const float4*)(tep + pc + 4));
        const float4 aL = make_float4(bL.x + tL.x, bL.y + tL.y, bL.z + tL.z, bL.w + tL.w);
        const float4 aH = make_float4(bH.x + tH.x, bH.y + tH.y, bH.z + tH.z, bH.w + tH.w);
        float* op0 = out + ((long)b0  * MM + m) * TT * EEE;
        float* op1 = out + ((long)b1v * MM + m) * TT * EEE;
        #pragma unroll
        for (int mt = 0; mt < 4; mt++) {
            const int r0 = mt * 16 + g;
            const int r1 = r0 + 8;
            float* p0 = ((r0 < TT) ? op0 : op1) + (long)(r0 & (TT - 1)) * EEE + pc;
            float* p1 = ((r1 < TT) ? op0 : op1) + (long)(r1 & (TT - 1)) * EEE + pc;
            *(float4*)p0 = make_float4(acc[mt][0][0] + aL.x, acc[mt][1][0] + aL.y,
                                       acc[mt][2][0] + aL.z, acc[mt][3][0] + aL.w);
            *(float4*)(p0 + 4) = make_float4(acc[mt][0][1] + aH.x, acc[mt][1][1] + aH.y,
                                             acc[mt][2][1] + aH.z, acc[mt][3][1] + aH.w);
            *(float4*)p1 = make_float4(acc[mt][0][2] + aL.x, acc[mt][1][2] + aL.y,
                                       acc[mt][2][2] + aL.z, acc[mt][3][2] + aL.w);
            *(float4*)(p1 + 4) = make_float4(acc[mt][0][3] + aH.x, acc[mt][1][3] + aH.y,
                                             acc[mt][2][3] + aH.z, acc[mt][3][3] + aH.w);
        }
    }
}

extern "C" void kernel_launch(void* const* d_in, const int* in_sizes, int n_in,
                              void* d_out, int out_size)
{
    const float* state   = (const float*)d_in[0];
    const int*   emb_ids = (const int*)  d_in[1];
    const float* W1      = (const float*)d_in[2];
    const float* b1      = (const float*)d_in[3];
    const float* W2      = (const float*)d_in[4];
    const float* b2      = (const float*)d_in[5];
    const float* te      = (const float*)d_in[6];
    float*       out     = (float*)d_out;

    pmst_prepass<<<1, 32>>>(emb_ids);

    cudaFuncSetAttribute(pmst_mma_kernel,
                         cudaFuncAttributeMaxDynamicSharedMemorySize, SMEM_BYTES);

    dim3 grid(MAXC, MM);
    pmst_mma_kernel<<<grid, 512, SMEM_BYTES>>>(state, W1, b1, W2, b2, te, out);
}

// round 15
// speedup vs baseline: 1.5120x; 1.0113x over previous
#include <cuda_runtime.h>
#include <cstdint>

#define MM   6
#define BB   128
#define TT   32
#define DINN 64
#define HHH  512
#define EEE  512
#define NEMB 32

#define MAXC       80
#define ROWS       64     // token rows per tile: 2 batches x 32
#define XS_STRIDE  68     // words; mod 32 = 4 -> conflict-free A-fragment LDS (tf32 GEMM1)
#define HS2_STRIDE 260    // fp16x2 words per row; mod 32 = 4 -> conflict-free A-frag LDS

// per-warp weight ring (shared region for both GEMMs)
#define WROW1_B  160                 // GEMM1 k8 stage row stride
#define WSTG1_B  (8 * WROW1_B)       // 1280
#define WROW2_B  176                 // GEMM2 k16 stage row stride (conflict-free LDS.128)
#define WSTG2_B  (16 * WROW2_B)      // 2816
#define WRING_B  (3 * WSTG2_B)       // 8448 (also covers 3*WSTG1_B)
#define XS_BYTES (ROWS * XS_STRIDE * 4)     // 17408
#define HS_BYTES (ROWS * HS2_STRIDE * 4)    // 66560
#define WR_OFF_B (XS_BYTES + HS_BYTES)      // 83968
#define SMEM_BYTES (WR_OFF_B + 16 * WRING_B)  // 219136

#define NBLOCKS 148

__device__ int g_chunk_b0[MAXC];
__device__ int g_chunk_b1[MAXC];
__device__ int g_chunk_e [MAXC];
__device__ int g_nchunks;
__device__ int g_tix;          // atomic tile ticket

__global__ void pmst_prepass(const int* __restrict__ emb_ids) {
    __shared__ int se[BB];
    for (int i = threadIdx.x; i < BB; i += 32) se[i] = emb_ids[i];
    __syncwarp();
    const int e = threadIdx.x;             // 0..31
    if (e == 0) g_tix = 0;
    int cnt = 0;
    for (int b = 0; b < BB; b++) cnt += (se[b] == e);
    int pairs = (cnt + 1) >> 1;
    int off = pairs;
    #pragma unroll
    for (int d = 1; d < 32; d <<= 1) {
        int v = __shfl_up_sync(0xFFFFFFFFu, off, d);
        if (e >= d) off += v;
    }
    if (e == 31) g_nchunks = off;
    int idx = off - pairs;
    int prev = -1;
    for (int b = 0; b < BB; b++) {
        if (se[b] == e) {
            if (prev < 0) prev = b;
            else { g_chunk_b0[idx] = prev; g_chunk_b1[idx] = b; g_chunk_e[idx] = e; idx++; prev = -1; }
        }
    }
    if (prev >= 0) { g_chunk_b0[idx] = prev; g_chunk_b1[idx] = prev; g_chunk_e[idx] = e; }
}

__device__ __forceinline__ uint32_t f2tf(float f) {
    uint32_t r; asm("cvt.rna.tf32.f32 %0, %1;" : "=r"(r) : "f"(f)); return r;
}
// pack two f32 -> fp16x2: lo = cvt(blo), hi = cvt(ahi)
__device__ __forceinline__ uint32_t packf16(float ahi, float blo) {
    uint32_t r; asm("cvt.rn.f16x2.f32 %0, %1, %2;" : "=r"(r) : "f"(ahi), "f"(blo)); return r;
}

__device__ __forceinline__ void mma8(float* d, const uint32_t* a, uint32_t b0, uint32_t b1) {
    asm volatile(
        "mma.sync.aligned.m16n8k8.row.col.f32.tf32.tf32.f32 "
        "{%0,%1,%2,%3}, {%4,%5,%6,%7}, {%8,%9}, {%0,%1,%2,%3};"
        : "+f"(d[0]), "+f"(d[1]), "+f"(d[2]), "+f"(d[3])
        : "r"(a[0]), "r"(a[1]), "r"(a[2]), "r"(a[3]), "r"(b0), "r"(b1));
}
__device__ __forceinline__ void mma16(float* d, const uint32_t* a, uint32_t b0, uint32_t b1) {
    asm volatile(
        "mma.sync.aligned.m16n8k16.row.col.f32.f16.f16.f32 "
        "{%0,%1,%2,%3}, {%4,%5,%6,%7}, {%8,%9}, {%0,%1,%2,%3};"
        : "+f"(d[0]), "+f"(d[1]), "+f"(d[2]), "+f"(d[3])
        : "r"(a[0]), "r"(a[1]), "r"(a[2]), "r"(a[3]), "r"(b0), "r"(b1));
}

#define CP_COMMIT() asm volatile("cp.async.commit_group;" ::: "memory")
#define CP_WAIT1()  asm volatile("cp.async.wait_group 1;" ::: "memory")
#define CP_WAIT0()  asm volatile("cp.async.wait_group 0;" ::: "memory")

// GEMM1 (k8): lane (g,tg) copies rows (tg, tg+4), cols 4g..4g+3 (2x16B)
__device__ __forceinline__ void issue_wslab8(uint32_t stage, const float* __restrict__ wrow,
                                             int g, int tg) {
    const float* sA = wrow + (long)tg * 512 + 4 * g;
    const float* sB = sA + 4 * 512;
    const uint32_t dA = stage + (uint32_t)(tg * WROW1_B + g * 16);
    const uint32_t dB = dA + 4 * WROW1_B;
    asm volatile("cp.async.cg.shared.global [%0], [%1], 16;" :: "r"(dA), "l"(sA) : "memory");
    asm volatile("cp.async.cg.shared.global [%0], [%1], 16;" :: "r"(dB), "l"(sB) : "memory");
}
// GEMM2 (k16): lane (g,tg) copies rows (2tg, 2tg+1, 2tg+8, 2tg+9), cols 4g..4g+3 (4x16B)
__device__ __forceinline__ void issue_wslab16(uint32_t stage, const float* __restrict__ wrow,
                                              int g, int tg) {
    const float* s0 = wrow + (long)(2 * tg) * 512 + 4 * g;
    const float* s1 = s0 + 512;
    const float* s2 = s0 + 8 * 512;
    const float* s3 = s2 + 512;
    const uint32_t d0 = stage + (uint32_t)(2 * tg * WROW2_B + g * 16);
    asm volatile("cp.async.cg.shared.global [%0], [%1], 16;" :: "r"(d0),               "l"(s0) : "memory");
    asm volatile("cp.async.cg.shared.global [%0], [%1], 16;" :: "r"(d0 + WROW2_B),     "l"(s1) : "memory");
    asm volatile("cp.async.cg.shared.global [%0], [%1], 16;" :: "r"(d0 + 8 * WROW2_B), "l"(s2) : "memory");
    asm volatile("cp.async.cg.shared.global [%0], [%1], 16;" :: "r"(d0 + 9 * WROW2_B), "l"(s3) : "memory");
}

__device__ __forceinline__ void lds128(float4& v, uint32_t addr) {
    asm volatile("ld.shared.v4.f32 {%0,%1,%2,%3}, [%4];"
                 : "=f"(v.x), "=f"(v.y), "=f"(v.z), "=f"(v.w) : "r"(addr));
}

// Persistent: 148 blocks x 512 threads; tiles dispatched via atomic ticket so the
// concurrent window is always ~148 CONSECUTIVE tiles (tix = c*MM + m, chunks
// emb-sorted) -> shared weight slices stay co-resident in L2 (fixes R12's desync)
// while the wave-quantization tail disappears. Body identical to R14.
__global__ __launch_bounds__(512, 1) void pmst_mma_kernel(
    const float* __restrict__ state,   // [B, T, M*DIN]
    const float* __restrict__ W1,      // [M, NEMB, DIN, H]
    const float* __restrict__ b1,      // [M, NEMB, H]
    const float* __restrict__ W2,      // [M, NEMB, H, E]
    const float* __restrict__ b2,      // [M, NEMB, E]
    const float* __restrict__ te,      // [M, E]
    float* __restrict__ out)           // [B, M*T, E]
{
    extern __shared__ uint32_t smu[];
    __shared__ int s_tix;
    uint32_t* Xs  = smu;                         // [ROWS][XS_STRIDE]  tf32 bits
    uint32_t* Hs2 = smu + ROWS * XS_STRIDE;      // [ROWS][HS2_STRIDE] fp16x2 k-pairs
    uint32_t smem_base;
    asm("{ .reg .u64 t; cvta.to.shared.u64 t, %1; cvt.u32.u64 %0, t; }"
        : "=r"(smem_base) : "l"((const void*)smu));

    const int tid  = threadIdx.x;
    const int wid  = tid >> 5;
    const int lane = tid & 31;
    const int g    = lane >> 2;    // 0..7
    const int tg   = lane & 3;     // 0..3

    const uint32_t wring = smem_base + WR_OFF_B + wid * WRING_B;
    const int ncol0 = wid * 32;
    const int total = g_nchunks * MM;

    float acc[4][4][4];   // [m-tile][n-tile][frag]

    for (;;) {
        if (tid == 0) s_tix = atomicAdd(&g_tix, 1);
        __syncthreads();             // broadcasts s_tix; also fences previous tile
        const int tix = s_tix;
        if (tix >= total) break;
        const int c = tix / MM;
        const int m = tix - c * MM;
        const int e   = g_chunk_e[c];
        const int b0  = g_chunk_b0[c];
        const int b1v = g_chunk_b1[c];

        const long me = (long)m * NEMB + e;
        const float* W1p = W1 + me * (DINN * HHH);
        const float* W2p = W2 + me * ((long)HHH * EEE);
        const float* b1p = b1 + me * HHH;
        const float* b2p = b2 + me * EEE;
        const float* tep = te + (long)m * EEE;
        const float* w1base = W1p + ncol0;
        const float* w2base = W2p + ncol0;

        // retire stale groups from previous tile before ring reuse
        CP_WAIT0();

        // ---- GEMM1 prologue: stages 0,1 in flight ----
        issue_wslab8(wring + 0 * WSTG1_B, w1base,           g, tg); CP_COMMIT();
        issue_wslab8(wring + 1 * WSTG1_B, w1base + 8 * HHH, g, tg); CP_COMMIT();

        // ---- Stage X (tf32) ----
        #pragma unroll
        for (int i = tid; i < ROWS * DINN; i += 512) {
            const int tr = i >> 6, k = i & 63;
            const int bb = (tr < TT) ? b0 : b1v;
            const int t  = tr & (TT - 1);
            Xs[tr * XS_STRIDE + k] =
                f2tf(__ldg(state + ((long)bb * TT + t) * (MM * DINN) + m * DINN + k));
        }
        __syncthreads();

        // ================= GEMM1 (tf32): H = relu(X @ W1 + b1) =================
        #pragma unroll
        for (int mt = 0; mt < 4; mt++)
            #pragma unroll
            for (int nt = 0; nt < 4; nt++)
                #pragma unroll
                for (int i = 0; i < 4; i++) acc[mt][nt][i] = 0.f;
        {
            int stg = 0;
            #pragma unroll
            for (int kc = 0; kc < 8; kc++) {
                CP_WAIT1();
                if (kc + 2 < 8) issue_wslab8(wring + ((stg + 2) % 3) * WSTG1_B,
                                             w1base + (long)(kc + 2) * 8 * HHH, g, tg);
                CP_COMMIT();

                uint32_t a[4][4];
                {
                    const uint32_t* xb = Xs + g * XS_STRIDE + tg + kc * 8;
                    #pragma unroll
                    for (int mt = 0; mt < 4; mt++) {
                        const uint32_t* xp = xb + mt * 16 * XS_STRIDE;
                        a[mt][0] = xp[0];
                        a[mt][1] = xp[8 * XS_STRIDE];
                        a[mt][2] = xp[4];
                        a[mt][3] = xp[8 * XS_STRIDE + 4];
                    }
                }
                float4 v0, v1;
                const uint32_t baseA = wring + stg * WSTG1_B + (uint32_t)(tg * WROW1_B + g * 16);
                lds128(v0, baseA);
                lds128(v1, baseA + 4 * WROW1_B);
                const uint32_t w0[4]  = { f2tf(v0.x), f2tf(v0.y), f2tf(v0.z), f2tf(v0.w) };
                const uint32_t w1f[4] = { f2tf(v1.x), f2tf(v1.y), f2tf(v1.z), f2tf(v1.w) };
                #pragma unroll
                for (int nt = 0; nt < 4; nt++)
                    #pragma unroll
                    for (int mt = 0; mt < 4; mt++) mma8(acc[mt][nt], a[mt], w0[nt], w1f[nt]);
                if (++stg == 3) stg = 0;
            }
        }

        // ---- GEMM2 prologue (k16 slabs 0,1; overlaps epilogue1 + barrier) ----
        CP_WAIT0();
        issue_wslab16(wring + 0 * WSTG2_B, w2base,            g, tg); CP_COMMIT();
        issue_wslab16(wring + 1 * WSTG2_B, w2base + 16 * EEE, g, tg); CP_COMMIT();

        // ---- epilogue1: relu + bias -> Hs2 (fp16x2, k-pairs along physical cols) ----
        {
            const int pc = ncol0 + 8 * tg;        // multiple of 8 -> word base pc/2
            const float4 bL = __ldg((const float4*)(b1p + pc));
            const float4 bH = __ldg((const float4*)(b1p + pc + 4));
            #pragma unroll
            for (int mt = 0; mt < 4; mt++) {
                const int r0 = mt * 16 + g;
                const int r1 = r0 + 8;
                uint4 wv;
                wv.x = packf16(fmaxf(acc[mt][1][0] + bL.y, 0.f), fmaxf(acc[mt][0][0] + bL.x, 0.f));
                wv.y = packf16(fmaxf(acc[mt][3][0] + bL.w, 0.f), fmaxf(acc[mt][2][0] + bL.z, 0.f));
                wv.z = packf16(fmaxf(acc[mt][1][1] + bH.y, 0.f), fmaxf(acc[mt][0][1] + bH.x, 0.f));
                wv.w = packf16(fmaxf(acc[mt][3][1] + bH.w, 0.f), fmaxf(acc[mt][2][1] + bH.z, 0.f));
                *(uint4*)(Hs2 + r0 * HS2_STRIDE + pc / 2) = wv;
                wv.x = packf16(fmaxf(acc[mt][1][2] + bL.y, 0.f), fmaxf(acc[mt][0][2] + bL.x, 0.f));
                wv.y = packf16(fmaxf(acc[mt][3][2] + bL.w, 0.f), fmaxf(acc[mt][2][2] + bL.z, 0.f));
                wv.z = packf16(fmaxf(acc[mt][1][3] + bH.y, 0.f), fmaxf(acc[mt][0][3] + bH.x, 0.f));
                wv.w = packf16(fmaxf(acc[mt][3][3] + bH.w, 0.f), fmaxf(acc[mt][2][3] + bH.z, 0.f));
                *(uint4*)(Hs2 + r1 * HS2_STRIDE + pc / 2) = wv;
            }
        }
        __syncthreads();

        // ================= GEMM2 (fp16 k16): Z = H @ W2 + b2 + te =================
        #pragma unroll
        for (int mt = 0; mt < 4; mt++)
            #pragma unroll
            for (int nt = 0; nt < 4; nt++)
                #pragma unroll
                for (int i = 0; i < 4; i++) acc[mt][nt][i] = 0.f;
        {
            int stg = 0;
            #pragma unroll 4
            for (int kc = 0; kc < 32; kc++) {     // k16 chunks
                CP_WAIT1();
                // prefetch FIRST (R9 discipline), into the 3rd ring stage
                if (kc + 2 < 32) issue_wslab16(wring + ((stg + 2) % 3) * WSTG2_B,
                                               w2base + (long)(kc + 2) * 16 * EEE, g, tg);
                CP_COMMIT();

                // A fragments (fp16x2 words)
                uint32_t a[4][4];
                {
                    const uint32_t* hb = Hs2 + g * HS2_STRIDE + kc * 8 + tg;
                    #pragma unroll
                    for (int mt = 0; mt < 4; mt++) {
                        const uint32_t* hp = hb + mt * 16 * HS2_STRIDE;
                        a[mt][0] = hp[0];
                        a[mt][1] = hp[8 * HS2_STRIDE];
                        a[mt][2] = hp[4];
                        a[mt][3] = hp[8 * HS2_STRIDE + 4];
                    }
                }
                // weight rows 2tg, 2tg+1, 2tg+8, 2tg+9 (f32), cols 4g..4g+3 — conflict-free
                float4 v0, v1, v2, v3;
                const uint32_t baseA = wring + stg * WSTG2_B + (uint32_t)(2 * tg * WROW2_B + g * 16);
                lds128(v0, baseA);
                lds128(v1, baseA + WROW2_B);
                lds128(v2, baseA + 8 * WROW2_B);
                lds128(v3, baseA + 9 * WROW2_B);

                const uint32_t bf0[4] = { packf16(v1.x, v0.x), packf16(v1.y, v0.y),
                                          packf16(v1.z, v0.z), packf16(v1.w, v0.w) };
                const uint32_t bf1[4] = { packf16(v3.x, v2.x), packf16(v3.y, v2.y),
                                          packf16(v3.z, v2.z), packf16(v3.w, v2.w) };
                #pragma unroll
                for (int nt = 0; nt < 4; nt++)
                    #pragma unroll
                    for (int mt = 0; mt < 4; mt++)
                        mma16(acc[mt][nt], a[mt], bf0[nt], bf1[nt]);
                if (++stg == 3) stg = 0;
            }
        }

        // ---- epilogue2: out[b, m*T + t, physical col] ----
        {
            const int pc = ncol0 + 8 * tg;
            const float4 bL = __ldg((const float4*)(b2p + pc));
            const float4 bH = __ldg((const float4*)(b2p + pc + 4));
            const float4 tL = __ldg((const float4*)(tep + pc));
            const float4 tH = __ldg((const float4*)(tep + pc + 4));
            const float4 aL = make_float4(bL.x + tL.x, bL.y + tL.y, bL.z + tL.z, bL.w + tL.w);
            const float4 aH = make_float4(bH.x + tH.x, bH.y + tH.y, bH.z + tH.z, bH.w + tH.w);
            float* op0 = out + ((long)b0  * MM + m) * TT * EEE;
            float* op1 = out + ((long)b1v * MM + m) * TT * EEE;
            #pragma unroll
            for (int mt = 0; mt < 4; mt++) {
                const int r0 = mt * 16 + g;
                const int r1 = r0 + 8;
                float* p0 = ((r0 < TT) ? op0 : op1) + (long)(r0 & (TT - 1)) * EEE + pc;
                float* p1 = ((r1 < TT) ? op0 : op1) + (long)(r1 & (TT - 1)) * EEE + pc;
                *(float4*)p0 = make_float4(acc[mt][0][0] + aL.x, acc[mt][1][0] + aL.y,
                                           acc[mt][2][0] + aL.z, acc[mt][3][0] + aL.w);
                *(float4*)(p0 + 4) = make_float4(acc[mt][0][1] + aH.x, acc[mt][1][1] + aH.y,
                                                 acc[mt][2][1] + aH.z, acc[mt][3][1] + aH.w);
                *(float4*)p1 = make_float4(acc[mt][0][2] + aL.x, acc[mt][1][2] + aL.y,
                                           acc[mt][2][2] + aL.z, acc[mt][3][2] + aL.w);
                *(float4*)(p1 + 4) = make_float4(acc[mt][0][3] + aH.x, acc[mt][1][3] + aH.y,
                                                 acc[mt][2][3] + aH.z, acc[mt][3][3] + aH.w);
            }
        }
    }
}

extern "C" void kernel_launch(void* const* d_in, const int* in_sizes, int n_in,
                              void* d_out, int out_size)
{
    const float* state   = (const float*)d_in[0];
    const int*   emb_ids = (const int*)  d_in[1];
    const float* W1      = (const float*)d_in[2];
    const float* b1      = (const float*)d_in[3];
    const float* W2      = (const float*)d_in[4];
    const float* b2      = (const float*)d_in[5];
    const float* te      = (const float*)d_in[6];
    float*       out     = (float*)d_out;

    pmst_prepass<<<1, 32>>>(emb_ids);

    cudaFuncSetAttribute(pmst_mma_kernel,
                         cudaFuncAttributeMaxDynamicSharedMemorySize, SMEM_BYTES);

    pmst_mma_kernel<<<NBLOCKS, 512, SMEM_BYTES>>>(state, W1, b1, W2, b2, te, out);
}